// round 5
// baseline (speedup 1.0000x reference)
#include <cuda_runtime.h>
#include <cuda_bf16.h>

// EquivariantLayer: edge attention (4 heads over 32-dim), scatter-mean, out-proj,
// LayerNorm, SiLU.  Restructured so the per-edge scatter is 4x float4 red.global
// instead of 128 scalar atomics, and Q/K/V projections collapse to a 3x3
// quadratic form per head.

#define N_NODES_MAX 100000
#define HEADS 4
#define HIDDEN 32
#define PROJ 128

// ---------------- device scratch (no allocations allowed) ----------------
__device__ float4 g_acc[N_NODES_MAX * HEADS];   // {attn_sum, S.x, S.y, S.z} per node/head

struct Pre {
    float G[HEADS][3][3];    // (Wq_h Wk_h^T) / sqrt(32)           36 floats
    float u[HEADS][3];       // (Wq_h bk_h + Wk_h bq_h)/sqrt(32)   12
    float c[HEADS];          // (bq_h . bk_h)/sqrt(32)              4
    float M[HEADS][3][32];   // Wv[c, h-slice] @ Wout[h-slice, j]  384
    float Bw[HEADS][32];     // bv[h-slice] @ Wout[h-slice, j]     128
};
__device__ Pre g_pre;        // 564 floats, layout: G | u | c | M | Bw
__device__ int g_is64;       // edge_index dtype flag

// ---------------- 0) detect edge_index dtype ----------------
__global__ void detect_kernel(const unsigned int* __restrict__ p) {
    // int64 little-endian: values in [0, 1e5) -> every hi-word is 0.
    // int32: 32 consecutive "hi" slots all being 0 has prob ~1e-160.
    bool is64 = true;
    #pragma unroll
    for (int i = 0; i < 32; i++)
        if (p[2 * i + 1] != 0u) is64 = false;
    g_is64 = is64 ? 1 : 0;
}

// ---------------- 1) precompute folded weights ----------------
__global__ void precompute_kernel(const float* __restrict__ Wq, const float* __restrict__ bq,
                                  const float* __restrict__ Wk, const float* __restrict__ bk,
                                  const float* __restrict__ Wv, const float* __restrict__ bv,
                                  const float* __restrict__ Wout) {
    const float SCALE = 0.17677669529663687f;  // 1/sqrt(32)
    int t = threadIdx.x;                        // 384 threads
    {   // M[h][c][j]
        int h = t / 96, rem = t % 96, cd = rem / 32, j = rem % 32;
        float s = 0.f;
        #pragma unroll
        for (int d = 0; d < 32; d++)
            s += Wv[cd * PROJ + h * 32 + d] * Wout[(h * 32 + d) * 32 + j];
        g_pre.M[h][cd][j] = s;
    }
    if (t < 128) {  // Bw[h][j]
        int h = t / 32, j = t % 32;
        float s = 0.f;
        #pragma unroll
        for (int d = 0; d < 32; d++)
            s += bv[h * 32 + d] * Wout[(h * 32 + d) * 32 + j];
        g_pre.Bw[h][j] = s;
    }
    if (t < 36) {   // G[h][a][b]
        int h = t / 9, rem = t % 9, a = rem / 3, b = rem % 3;
        float s = 0.f;
        #pragma unroll
        for (int d = 0; d < 32; d++)
            s += Wq[a * PROJ + h * 32 + d] * Wk[b * PROJ + h * 32 + d];
        g_pre.G[h][a][b] = s * SCALE;
    }
    if (t < 12) {   // u[h][a]
        int h = t / 3, a = t % 3;
        float s = 0.f;
        #pragma unroll
        for (int d = 0; d < 32; d++)
            s += Wq[a * PROJ + h * 32 + d] * bk[h * 32 + d]
               + Wk[a * PROJ + h * 32 + d] * bq[h * 32 + d];
        g_pre.u[h][a] = s * SCALE;
    }
    if (t < 4) {    // c[h]
        float s = 0.f;
        #pragma unroll
        for (int d = 0; d < 32; d++)
            s += bq[t * 32 + d] * bk[t * 32 + d];
        g_pre.c[t] = s * SCALE;
    }
}

// ---------------- 2) zero accumulators ----------------
__global__ void zero_acc_kernel(int n) {
    int i = blockIdx.x * blockDim.x + threadIdx.x;
    if (i < n) g_acc[i] = make_float4(0.f, 0.f, 0.f, 0.f);
}

// ---------------- 3) per-edge: scores -> softmax -> red.v4 scatter ----------------
__global__ void __launch_bounds__(256) edge_kernel(const float* __restrict__ pos,
                                                   const void* __restrict__ eidx, int E) {
    __shared__ float sP[52];  // [0:36) G, [36:48) u, [48:52) c  (matches Pre layout)
    int t = threadIdx.x;
    if (t < 52) sP[t] = ((const float*)&g_pre)[t];
    __syncthreads();

    int e = blockIdx.x * blockDim.x + t;
    if (e >= E) return;

    int r, c;
    if (g_is64) {
        const long long* p = (const long long*)eidx;
        r = (int)p[e];
        c = (int)p[(long long)E + e];
    } else {
        const int* p = (const int*)eidx;
        r = p[e];
        c = p[E + e];
    }

    float x = pos[3 * r + 0] - pos[3 * c + 0];
    float y = pos[3 * r + 1] - pos[3 * c + 1];
    float z = pos[3 * r + 2] - pos[3 * c + 2];

    float s[HEADS];
    float m = -1e30f;
    #pragma unroll
    for (int h = 0; h < HEADS; h++) {
        const float* G = &sP[h * 9];
        float gx = G[0] * x + G[1] * y + G[2] * z;
        float gy = G[3] * x + G[4] * y + G[5] * z;
        float gz = G[6] * x + G[7] * y + G[8] * z;
        float v = x * gx + y * gy + z * gz
                + sP[36 + h * 3 + 0] * x + sP[36 + h * 3 + 1] * y + sP[36 + h * 3 + 2] * z
                + sP[48 + h];
        s[h] = v;
        m = fmaxf(m, v);
    }
    float tsum = 0.f;
    #pragma unroll
    for (int h = 0; h < HEADS; h++) { s[h] = __expf(s[h] - m); tsum += s[h]; }
    float inv = 1.0f / tsum;

    float4* base = &g_acc[(long long)c * HEADS];
    #pragma unroll
    for (int h = 0; h < HEADS; h++) {
        float a = s[h] * inv;
        float4* p = base + h;
        asm volatile("red.global.add.v4.f32 [%0], {%1, %2, %3, %4};"
                     :: "l"(p), "f"(a), "f"(a * x), "f"(a * y), "f"(a * z)
                     : "memory");
    }
}

// ---------------- 4) per-node: reconstruct, project, LN, SiLU ----------------
__global__ void __launch_bounds__(256) node_kernel(float* __restrict__ out,
                                                   const float* __restrict__ bout,
                                                   const float* __restrict__ gamma,
                                                   const float* __restrict__ beta, int N) {
    __shared__ float sM[512];  // M (384) then Bw (128); Pre offset 52 floats
    const float* src = ((const float*)&g_pre) + 52;
    for (int i = threadIdx.x; i < 512; i += blockDim.x) sM[i] = src[i];
    __syncthreads();

    int n = (blockIdx.x * blockDim.x + threadIdx.x) >> 5;
    int j = threadIdx.x & 31;
    if (n >= N) return;

    float4 a0 = g_acc[n * 4 + 0];
    float4 a1 = g_acc[n * 4 + 1];
    float4 a2 = g_acc[n * 4 + 2];
    float4 a3 = g_acc[n * 4 + 3];

    float cnt = a0.x + a1.x + a2.x + a3.x;          // == edge count (softmax sums to 1)
    float inv = 1.0f / fmaxf(cnt, 1.0f);

    float acc =
        a0.y * sM[0 * 96 + 0 * 32 + j] + a0.z * sM[0 * 96 + 1 * 32 + j] + a0.w * sM[0 * 96 + 2 * 32 + j] + a0.x * sM[384 + 0 * 32 + j] +
        a1.y * sM[1 * 96 + 0 * 32 + j] + a1.z * sM[1 * 96 + 1 * 32 + j] + a1.w * sM[1 * 96 + 2 * 32 + j] + a1.x * sM[384 + 1 * 32 + j] +
        a2.y * sM[2 * 96 + 0 * 32 + j] + a2.z * sM[2 * 96 + 1 * 32 + j] + a2.w * sM[2 * 96 + 2 * 32 + j] + a2.x * sM[384 + 2 * 32 + j] +
        a3.y * sM[3 * 96 + 0 * 32 + j] + a3.z * sM[3 * 96 + 1 * 32 + j] + a3.w * sM[3 * 96 + 2 * 32 + j] + a3.x * sM[384 + 3 * 32 + j];

    float o = acc * inv + bout[j];

    // LayerNorm over the 32 lanes of this warp
    float mu = o;
    #pragma unroll
    for (int off = 16; off > 0; off >>= 1) mu += __shfl_xor_sync(0xffffffffu, mu, off);
    mu *= (1.0f / 32.0f);
    float d = o - mu;
    float var = d * d;
    #pragma unroll
    for (int off = 16; off > 0; off >>= 1) var += __shfl_xor_sync(0xffffffffu, var, off);
    var *= (1.0f / 32.0f);

    float yv = d * rsqrtf(var + 1e-5f) * gamma[j] + beta[j];
    out[(long long)n * 32 + j] = yv / (1.0f + __expf(-yv));   // SiLU
}

// ---------------- launch ----------------
extern "C" void kernel_launch(void* const* d_in, const int* in_sizes, int n_in,
                              void* d_out, int out_size) {
    const float* pos   = (const float*)d_in[0];
    const void*  eidx  = d_in[1];
    const float* Wq    = (const float*)d_in[2];
    const float* bq    = (const float*)d_in[3];
    const float* Wk    = (const float*)d_in[4];
    const float* bk    = (const float*)d_in[5];
    const float* Wv    = (const float*)d_in[6];
    const float* bv    = (const float*)d_in[7];
    const float* Wout  = (const float*)d_in[8];
    const float* bout  = (const float*)d_in[9];
    const float* gamma = (const float*)d_in[10];
    const float* beta  = (const float*)d_in[11];

    int N = in_sizes[0] / 3;      // 100000
    int E = in_sizes[1] / 2;      // 500000 (element count is dtype-independent)
    if (N > N_NODES_MAX) N = N_NODES_MAX;

    detect_kernel<<<1, 32>>>((const unsigned int*)eidx);
    precompute_kernel<<<1, 384>>>(Wq, bq, Wk, bk, Wv, bv, Wout);
    int nacc = N * HEADS;
    zero_acc_kernel<<<(nacc + 255) / 256, 256>>>(nacc);
    edge_kernel<<<(E + 255) / 256, 256>>>(pos, eidx, E);
    node_kernel<<<(N + 7) / 8, 256>>>((float*)d_out, bout, gamma, beta, N);
}

// round 7
// speedup vs baseline: 1.5841x; 1.5841x over previous
#include <cuda_runtime.h>
#include <cuda_bf16.h>

// EquivariantLayer: edge attention (4 heads), scatter-mean, out-proj, LN, SiLU.
// R6: ILP-4 edge kernel with vectorized index loads + float4-packed position
// gathers; setup work (detect/precompute/zero/pos-pack) fused into one launch.

#define N_NODES_MAX 100000
#define HEADS 4
#define HIDDEN 32
#define PROJ 128
#define EPT 4   // edges per thread

// ---------------- device scratch (no allocations allowed) ----------------
__device__ float4 g_acc[N_NODES_MAX * HEADS];   // {attn_sum, S.x, S.y, S.z}
__device__ float4 g_pos4[N_NODES_MAX];          // packed positions {x,y,z,0}

struct Pre {
    float G[HEADS][3][3];    // (Wq_h Wk_h^T)/sqrt(32)            36 floats
    float u[HEADS][3];       // (Wq_h bk_h + Wk_h bq_h)/sqrt(32)  12
    float c[HEADS];          // (bq_h . bk_h)/sqrt(32)             4
    float M[HEADS][3][32];   // Wv[c, h-slice] @ Wout[h-slice, j] 384
    float Bw[HEADS][32];     // bv[h-slice] @ Wout[h-slice, j]    128
};
__device__ Pre g_pre;        // 564 floats: G | u | c | M | Bw
__device__ int g_is64;

// ---------------- 1) fused setup: detect + precompute + zero + pos-pack ----
__global__ void __launch_bounds__(384) setup_kernel(
        const float* __restrict__ pos, const void* __restrict__ eidx,
        const float* __restrict__ Wq, const float* __restrict__ bq,
        const float* __restrict__ Wk, const float* __restrict__ bk,
        const float* __restrict__ Wv, const float* __restrict__ bv,
        const float* __restrict__ Wout, int N, int nacc) {
    int g = blockIdx.x * 384 + threadIdx.x;
    if (g < nacc) g_acc[g] = make_float4(0.f, 0.f, 0.f, 0.f);
    if (g < N)
        g_pos4[g] = make_float4(pos[3 * g + 0], pos[3 * g + 1], pos[3 * g + 2], 0.f);

    if (blockIdx.x != 0) return;
    int t = threadIdx.x;

    // dtype detect (warp 0): int64 in [0,1e5) -> every hi-word zero
    if (t < 32) {
        const unsigned int* p = (const unsigned int*)eidx;
        bool hz = (p[2 * t + 1] == 0u);
        unsigned int mask = __ballot_sync(0xffffffffu, hz);
        if (t == 0) g_is64 = (mask == 0xffffffffu) ? 1 : 0;
    }

    const float SCALE = 0.17677669529663687f;  // 1/sqrt(32)
    {   // M[h][c][j], 384 threads
        int h = t / 96, rem = t % 96, cd = rem / 32, j = rem % 32;
        float s = 0.f;
        #pragma unroll
        for (int d = 0; d < 32; d++)
            s += Wv[cd * PROJ + h * 32 + d] * Wout[(h * 32 + d) * 32 + j];
        g_pre.M[h][cd][j] = s;
    }
    if (t < 128) {  // Bw[h][j]
        int h = t / 32, j = t % 32;
        float s = 0.f;
        #pragma unroll
        for (int d = 0; d < 32; d++)
            s += bv[h * 32 + d] * Wout[(h * 32 + d) * 32 + j];
        g_pre.Bw[h][j] = s;
    }
    if (t < 36) {   // G[h][a][b]
        int h = t / 9, rem = t % 9, a = rem / 3, b = rem % 3;
        float s = 0.f;
        #pragma unroll
        for (int d = 0; d < 32; d++)
            s += Wq[a * PROJ + h * 32 + d] * Wk[b * PROJ + h * 32 + d];
        g_pre.G[h][a][b] = s * SCALE;
    }
    if (t < 12) {   // u[h][a]
        int h = t / 3, a = t % 3;
        float s = 0.f;
        #pragma unroll
        for (int d = 0; d < 32; d++)
            s += Wq[a * PROJ + h * 32 + d] * bk[h * 32 + d]
               + Wk[a * PROJ + h * 32 + d] * bq[h * 32 + d];
        g_pre.u[h][a] = s * SCALE;
    }
    if (t < 4) {    // c[h]
        float s = 0.f;
        #pragma unroll
        for (int d = 0; d < 32; d++)
            s += bq[t * 32 + d] * bk[t * 32 + d];
        g_pre.c[t] = s * SCALE;
    }
}

// ---------------- 2) per-edge: scores -> softmax -> red.v4 scatter ----------
__device__ __forceinline__ void edge_body(const float* sP, int c, float x, float y, float z) {
    float s[HEADS];
    float m = -1e30f;
    #pragma unroll
    for (int h = 0; h < HEADS; h++) {
        const float* G = &sP[h * 9];
        float gx = G[0] * x + G[1] * y + G[2] * z;
        float gy = G[3] * x + G[4] * y + G[5] * z;
        float gz = G[6] * x + G[7] * y + G[8] * z;
        float v = x * gx + y * gy + z * gz
                + sP[36 + h * 3 + 0] * x + sP[36 + h * 3 + 1] * y + sP[36 + h * 3 + 2] * z
                + sP[48 + h];
        s[h] = v;
        m = fmaxf(m, v);
    }
    float tsum = 0.f;
    #pragma unroll
    for (int h = 0; h < HEADS; h++) { s[h] = __expf(s[h] - m); tsum += s[h]; }
    float inv = 1.0f / tsum;

    float4* base = &g_acc[(long long)c * HEADS];
    #pragma unroll
    for (int h = 0; h < HEADS; h++) {
        float a = s[h] * inv;
        float4* p = base + h;
        asm volatile("red.global.add.v4.f32 [%0], {%1, %2, %3, %4};"
                     :: "l"(p), "f"(a), "f"(a * x), "f"(a * y), "f"(a * z)
                     : "memory");
    }
}

__global__ void __launch_bounds__(256) edge_kernel(const void* __restrict__ eidx, int E) {
    __shared__ float sP[52];  // [0:36) G, [36:48) u, [48:52) c
    int t = threadIdx.x;
    if (t < 52) sP[t] = ((const float*)&g_pre)[t];
    __syncthreads();

    int e0 = (blockIdx.x * 256 + t) * EPT;
    if (e0 >= E) return;
    int is64 = g_is64;
    int nleft = E - e0;

    if (nleft >= EPT) {
        int r[EPT], c[EPT];
        if (is64) {
            const long long* p = (const long long*)eidx;
            if (((unsigned)E & 1u) == 0u) {   // e0 is always even
                longlong2 A = *(const longlong2*)(p + e0);
                longlong2 B = *(const longlong2*)(p + e0 + 2);
                longlong2 C = *(const longlong2*)(p + E + e0);
                longlong2 D = *(const longlong2*)(p + E + e0 + 2);
                r[0] = (int)A.x; r[1] = (int)A.y; r[2] = (int)B.x; r[3] = (int)B.y;
                c[0] = (int)C.x; c[1] = (int)C.y; c[2] = (int)D.x; c[3] = (int)D.y;
            } else {
                #pragma unroll
                for (int i = 0; i < EPT; i++) {
                    r[i] = (int)p[e0 + i];
                    c[i] = (int)p[(long long)E + e0 + i];
                }
            }
        } else {
            const int* p = (const int*)eidx;
            if (((unsigned)E & 3u) == 0u) {   // e0 is always a multiple of 4
                int4 A = *(const int4*)(p + e0);
                int4 C = *(const int4*)(p + E + e0);
                r[0] = A.x; r[1] = A.y; r[2] = A.z; r[3] = A.w;
                c[0] = C.x; c[1] = C.y; c[2] = C.z; c[3] = C.w;
            } else {
                #pragma unroll
                for (int i = 0; i < EPT; i++) { r[i] = p[e0 + i]; c[i] = p[E + e0 + i]; }
            }
        }

        // batch the 8 gathers for maximum MLP before any compute
        float4 Pr[EPT], Pc[EPT];
        #pragma unroll
        for (int i = 0; i < EPT; i++) Pr[i] = __ldg(&g_pos4[r[i]]);
        #pragma unroll
        for (int i = 0; i < EPT; i++) Pc[i] = __ldg(&g_pos4[c[i]]);

        #pragma unroll
        for (int i = 0; i < EPT; i++)
            edge_body(sP, c[i], Pr[i].x - Pc[i].x, Pr[i].y - Pc[i].y, Pr[i].z - Pc[i].z);
    } else {
        for (int i = 0; i < nleft; i++) {
            int r, c;
            if (is64) {
                const long long* p = (const long long*)eidx;
                r = (int)p[e0 + i];
                c = (int)p[(long long)E + e0 + i];
            } else {
                const int* p = (const int*)eidx;
                r = p[e0 + i];
                c = p[E + e0 + i];
            }
            float4 Pr = __ldg(&g_pos4[r]);
            float4 Pc = __ldg(&g_pos4[c]);
            edge_body(sP, c, Pr.x - Pc.x, Pr.y - Pc.y, Pr.z - Pc.z);
        }
    }
}

// ---------------- 3) per-node: reconstruct, project, LN, SiLU ----------------
__global__ void __launch_bounds__(256) node_kernel(float* __restrict__ out,
                                                   const float* __restrict__ bout,
                                                   const float* __restrict__ gamma,
                                                   const float* __restrict__ beta, int N) {
    __shared__ float sM[512];   // M (384) then Bw (128)
    __shared__ float sB[96];    // bout | gamma | beta
    const float* src = ((const float*)&g_pre) + 52;
    for (int i = threadIdx.x; i < 512; i += blockDim.x) sM[i] = src[i];
    if (threadIdx.x < 32) {
        sB[threadIdx.x]      = bout[threadIdx.x];
        sB[32 + threadIdx.x] = gamma[threadIdx.x];
        sB[64 + threadIdx.x] = beta[threadIdx.x];
    }
    __syncthreads();

    int n = (blockIdx.x * blockDim.x + threadIdx.x) >> 5;
    int j = threadIdx.x & 31;
    if (n >= N) return;

    float4 a0 = g_acc[n * 4 + 0];
    float4 a1 = g_acc[n * 4 + 1];
    float4 a2 = g_acc[n * 4 + 2];
    float4 a3 = g_acc[n * 4 + 3];

    float cnt = a0.x + a1.x + a2.x + a3.x;   // == edge count (softmax sums to 1)
    float inv = 1.0f / fmaxf(cnt, 1.0f);

    float acc =
        a0.y * sM[ 0 + j] + a0.z * sM[ 32 + j] + a0.w * sM[ 64 + j] + a0.x * sM[384 + j] +
        a1.y * sM[96 + j] + a1.z * sM[128 + j] + a1.w * sM[160 + j] + a1.x * sM[416 + j] +
        a2.y * sM[192 + j] + a2.z * sM[224 + j] + a2.w * sM[256 + j] + a2.x * sM[448 + j] +
        a3.y * sM[288 + j] + a3.z * sM[320 + j] + a3.w * sM[352 + j] + a3.x * sM[480 + j];

    float o = acc * inv + sB[j];

    float mu = o;
    #pragma unroll
    for (int off = 16; off > 0; off >>= 1) mu += __shfl_xor_sync(0xffffffffu, mu, off);
    mu *= (1.0f / 32.0f);
    float d = o - mu;
    float var = d * d;
    #pragma unroll
    for (int off = 16; off > 0; off >>= 1) var += __shfl_xor_sync(0xffffffffu, var, off);
    var *= (1.0f / 32.0f);

    float yv = d * rsqrtf(var + 1e-5f) * sB[32 + j] + sB[64 + j];
    out[(long long)n * 32 + j] = yv / (1.0f + __expf(-yv));   // SiLU
}

// ---------------- launch ----------------
extern "C" void kernel_launch(void* const* d_in, const int* in_sizes, int n_in,
                              void* d_out, int out_size) {
    const float* pos   = (const float*)d_in[0];
    const void*  eidx  = d_in[1];
    const float* Wq    = (const float*)d_in[2];
    const float* bq    = (const float*)d_in[3];
    const float* Wk    = (const float*)d_in[4];
    const float* bk    = (const float*)d_in[5];
    const float* Wv    = (const float*)d_in[6];
    const float* bv    = (const float*)d_in[7];
    const float* Wout  = (const float*)d_in[8];
    const float* bout  = (const float*)d_in[9];
    const float* gamma = (const float*)d_in[10];
    const float* beta  = (const float*)d_in[11];

    int N = in_sizes[0] / 3;      // 100000
    int E = in_sizes[1] / 2;      // 500000
    if (N > N_NODES_MAX) N = N_NODES_MAX;
    int nacc = N * HEADS;

    setup_kernel<<<(nacc + 383) / 384, 384>>>(pos, eidx, Wq, bq, Wk, bk, Wv, bv, Wout, N, nacc);
    edge_kernel<<<(E + 256 * EPT - 1) / (256 * EPT), 256>>>(eidx, E);
    node_kernel<<<(N + 7) / 8, 256>>>((float*)d_out, bout, gamma, beta, N);
}